// round 9
// baseline (speedup 1.0000x reference)
#include <cuda_runtime.h>
#include <math.h>

#define EPSV 1e-5f
#define VFLOOR 1e-6f

// Fixed shape: B=4, L=4096, D=2048, G=16 (gs=128). Chunk = 8 rows.
constexpr int Lc   = 4096;
constexpr int Gc   = 16;
constexpr int Dc   = 2048;
constexpr int CH   = 8;
constexpr int NCH  = Lc / CH;     // 512 chunks per batch
constexpr int MAXB = 8;

__device__ float d_S   [MAXB * Gc * NCH];
__device__ float d_Q   [MAXB * Gc * NCH];
__device__ float d_C   [MAXB * NCH];
__device__ int   d_flag[MAXB * NCH];

__global__ void k_init(int n) {
    const int i = blockIdx.x * blockDim.x + threadIdx.x;
    if (i < n) d_flag[i] = 0;
}

__device__ __forceinline__ int ld_acq(const int* p) {
    int v;
    asm volatile("ld.acquire.gpu.global.b32 %0, [%1];" : "=r"(v) : "l"(p));
    return v;
}
__device__ __forceinline__ void st_rel(int* p, int v) {
    asm volatile("st.release.gpu.global.b32 [%0], %1;" :: "l"(p), "r"(v) : "memory");
}

// ---------------------------------------------------------------------------
// Fused single-pass kernel: x read once (registers), chain-free sum-lookback.
// Block = one 8-row chunk; warp g owns group g.
// ---------------------------------------------------------------------------
__global__ void __launch_bounds__(512, 2)
k_fused(const float* __restrict__ x,
        const int*   __restrict__ pcnt,
        const float* __restrict__ pmean,
        const float* __restrict__ pvar,
        const int*   __restrict__ pmask,
        const float* __restrict__ wgt,
        const float* __restrict__ bias,
        float*       __restrict__ outF,
        int B, int writeTail, long long tailOff)
{
    const unsigned FULL = 0xffffffffu;
    const int tid  = threadIdx.x;
    const int b    = blockIdx.x >> 9;        // / NCH
    const int ch   = blockIdx.x & (NCH - 1);
    const int lane = tid & 31;
    const int g    = tid >> 5;
    const int rowBase = b * Lc + ch * CH;
    const int fb   = b * NCH;

    // ---- load x chunk into registers (MLP=8) + affine params --------------
    const float4* xr = (const float4*)x;
    float4 v[CH];
    #pragma unroll
    for (int r = 0; r < CH; r++)
        v[r] = xr[(size_t)(rowBase + r) * (Dc / 4) + g * 32 + lane];

    float4 wv = ((const float4*)wgt)[g * 32 + lane];
    float4 bv = ((const float4*)bias)[g * 32 + lane];
    wv.x += 1.f; wv.y += 1.f; wv.z += 1.f; wv.w += 1.f;

    // ---- Phase A: per-chunk aggregates (S, Q, C); lane r keeps row r's gm -
    float S = 0.f, Q = 0.f, C = 0.f, mygm = 0.f;
    #pragma unroll
    for (int r = 0; r < CH; r++) {
        float s = (v[r].x + v[r].y) + (v[r].z + v[r].w);
        #pragma unroll
        for (int o = 16; o > 0; o >>= 1)
            s += __shfl_xor_sync(FULL, s, o);
        const float gm = s * (1.0f / 128.0f);
        if (lane == r) mygm = gm;
        const float vr = pmask[rowBase + r] ? 1.0f : 0.0f;
        S += gm * vr;
        Q += gm * gm * vr;
        C += vr;
    }
    if (lane == 0) {
        const int idx = (b * Gc + g) * NCH + ch;
        d_S[idx] = S;
        d_Q[idx] = Q;
        if (g == 0) d_C[fb + ch] = C;
    }
    __syncthreads();
    if (tid == 0) {
        __threadfence();
        st_rel(&d_flag[fb + ch], 1);      // no chain: depends only on phase A
    }

    // ---- Phase B: sum predecessor aggregates (flags almost always set) ----
    float prefS = 0.f, prefQ = 0.f, prefC = 0.f;
    {
        const int abase = (b * Gc + g) * NCH;
        for (int j = lane; j < ch; j += 32) {
            while (ld_acq(&d_flag[fb + j]) == 0) __nanosleep(30);
            prefS += d_S[abase + j];
            prefQ += d_Q[abase + j];
            prefC += d_C[fb + j];
        }
        #pragma unroll
        for (int o = 16; o > 0; o >>= 1) {
            prefS += __shfl_xor_sync(FULL, prefS, o);
            prefQ += __shfl_xor_sync(FULL, prefQ, o);
            prefC += __shfl_xor_sync(FULL, prefC, o);
        }
    }

    // ---- in-chunk inclusive scan over the 8 rows (lanes 0..7) -------------
    const float myv = (lane < CH) ? (pmask[rowBase + (lane & (CH - 1))] ? 1.0f : 0.0f) : 0.0f;
    float sS = mygm * myv;
    float sQ = mygm * mygm * myv;
    float sC = myv;
    #pragma unroll
    for (int o = 1; o < CH; o <<= 1) {
        const float a0 = __shfl_up_sync(FULL, sS, o);
        const float a1 = __shfl_up_sync(FULL, sQ, o);
        const float a2 = __shfl_up_sync(FULL, sC, o);
        if (lane >= o) { sS += a0; sQ += a1; sC += a2; }
    }

    // ---- Chan closed-form streaming stats (validated R7) ------------------
    const float pc     = (float)pcnt[b];
    const float pmeanv = pmean[b * Gc + g];
    const float pvarv  = pvar [b * Gc + g];
    const float psum   = pmeanv * pc;
    const float pm2    = pvarv * fmaxf(pc, 1.0f);

    const float S_t = prefS + sS;
    const float Q_t = prefQ + sQ;
    const float c_t = prefC + sC;
    const float count_t = pc + c_t;

    float mean_t = pmeanv, var = pvarv;
    if (count_t > 0.0f) {
        mean_t = (psum + S_t) / fmaxf(count_t, 1.0f);
        float sumdd = 0.0f;
        if (c_t > 0.0f) {
            const float bm  = S_t / c_t;
            const float m2b = Q_t - bm * S_t;
            const float dlt = bm - pmeanv;
            sumdd = m2b + dlt * dlt * (pc * c_t / (pc + c_t));
        }
        var = (pm2 + sumdd) / fmaxf(count_t, 1.0f);
    }
    var = fmaxf(var, VFLOOR);
    const float myrstd = rsqrtf(var + EPSV);

    if (writeTail && ch == NCH - 1 && lane == CH - 1) {
        outF[tailOff + B + b * Gc + g]                  = mean_t;
        outF[tailOff + B + (size_t)B * Gc + b * Gc + g] = var;
        if (g == 0) outF[tailOff + b] = count_t;   // new_count
    }

    // ---- Phase C: normalize from registers, write y -----------------------
    float4* yr = (float4*)outF;
    #pragma unroll
    for (int r = 0; r < CH; r++) {
        const float mn = __shfl_sync(FULL, mean_t, r);
        const float rs = __shfl_sync(FULL, myrstd, r);
        float4 o;
        o.x = (v[r].x - mn) * rs * wv.x + bv.x;
        o.y = (v[r].y - mn) * rs * wv.y + bv.y;
        o.z = (v[r].z - mn) * rs * wv.z + bv.z;
        o.w = (v[r].w - mn) * rs * wv.w + bv.w;
        yr[(size_t)(rowBase + r) * (Dc / 4) + g * 32 + lane] = o;
    }
}

// ---------------------------------------------------------------------------
extern "C" void kernel_launch(void* const* d_in, const int* in_sizes, int n_in,
                              void* d_out, int out_size)
{
    const float* x     = (const float*)d_in[0];
    const int*   pcnt  = (const int*)d_in[1];
    const float* pmean = (const float*)d_in[2];
    const float* pvar  = (const float*)d_in[3];
    const int*   pmask = (const int*)d_in[4];
    const float* wgt   = (const float*)d_in[5];
    const float* bias  = (const float*)d_in[6];
    float*       outF  = (float*)d_out;

    const int B = in_sizes[1];
    const int G = in_sizes[2] / B;     // 16
    const int D = in_sizes[5];         // 2048
    const int L = in_sizes[4] / B;     // 4096
    (void)G; (void)D; (void)L;

    const long long BLD = (long long)B * L * D;
    const long long expected = BLD + B + 2LL * B * G;
    const int writeTail = (out_size >= expected) ? 1 : 0;

    const int nflags = B * NCH;
    k_init <<<(nflags + 511) / 512, 512>>>(nflags);
    k_fused<<<B * NCH, 512>>>(x, pcnt, pmean, pvar, pmask, wgt, bias,
                              outF, B, writeTail, BLD);
}